// round 3
// baseline (speedup 1.0000x reference)
#include <cuda_runtime.h>
#include <cuda_fp16.h>
#include <cstdint>
#include <cstddef>

// Problem dims
#define S_DIM  128
#define I_DIM  384
#define INJ    256   // IN_DIM
#define PD     32    // PROJ_DIM
#define PD2    64
#define F_DIM  128   // OUT_DIM
#define MROWS  (I_DIM*PD)       // 12288

// ---------------- scratch (device globals; no allocation allowed) ----------
__device__ __align__(16) __half g_L[MROWS * S_DIM];            // [(i*32+d)][s]  3.1 MB
__device__ __align__(16) __half g_R[MROWS * S_DIM];            // [(j*32+e)][s]  3.1 MB
__device__ __align__(16) __half g_Wt[F_DIM * 1024];            // [f][(d*32+e)]  256 KB
__device__ __align__(16) __half g_G[(size_t)I_DIM * I_DIM * 1024]; // [i][j][d][e] 302 MB
__device__ float g_norm[I_DIM * I_DIM];

// ---------------- K1: layernorm + projection + mask -> L,R (fp16 rn) -------
__global__ __launch_bounds__(256) void k_ln_proj(const float* __restrict__ x,
                                                 const float* __restrict__ mask,
                                                 const float* __restrict__ Wp,
                                                 const float* __restrict__ bp) {
    int row = blockIdx.x;              // row = s*384 + i
    int s = row / I_DIM;
    int i = row - s * I_DIM;
    int t = threadIdx.x;

    __shared__ float xs[INJ];
    __shared__ float rs[8], rq[8];
    __shared__ float pacc[256];

    float v = x[(size_t)row * INJ + t];
    float sum = v, sq = v * v;
#pragma unroll
    for (int o = 16; o > 0; o >>= 1) {
        sum += __shfl_xor_sync(0xffffffffu, sum, o);
        sq  += __shfl_xor_sync(0xffffffffu, sq, o);
    }
    if ((t & 31) == 0) { rs[t >> 5] = sum; rq[t >> 5] = sq; }
    __syncthreads();
    float ts = 0.f, tq = 0.f;
#pragma unroll
    for (int w = 0; w < 8; w++) { ts += rs[w]; tq += rq[w]; }
    float mean = ts * (1.f / INJ);
    float var  = tq * (1.f / INJ) - mean * mean;
    float rstd = rsqrtf(var + 1e-5f);
    xs[t] = (v - mean) * rstd;
    __syncthreads();

    // 4 threads cooperate per output column (64 columns)
    int c = t & 63, q = t >> 6;
    float acc = 0.f;
    int k0 = q * 64;
#pragma unroll 4
    for (int k = k0; k < k0 + 64; k++) acc += xs[k] * Wp[k * PD2 + c];
    pacc[t] = acc;
    __syncthreads();
    if (q == 0) {
        float tot = pacc[c] + pacc[c + 64] + pacc[c + 128] + pacc[c + 192] + bp[c];
        tot *= mask[row];
        __half h = __float2half_rn(tot);
        if (c < PD) g_L[((size_t)(i * PD + c)) * S_DIM + s] = h;
        else        g_R[((size_t)(i * PD + (c - PD))) * S_DIM + s] = h;
    }
}

// ---------------- K2: transpose out_weights -> Wt[f][d*32+e] (fp16 rn) -----
__global__ __launch_bounds__(256) void k_wt(const float* __restrict__ w) {
    int idx = blockIdx.x * 256 + threadIdx.x;   // idx = f*1024 + de
    int f  = idx >> 10;
    int de = idx & 1023;
    g_Wt[idx] = __float2half_rn(w[de * F_DIM + f]);
}

// ---------------- K3: norm[i][j] = sum_s mask[s][i]*mask[s][j] -------------
__global__ __launch_bounds__(256) void k_norm(const float* __restrict__ mask) {
    __shared__ float mi[16], mj[16];
    int t = threadIdx.x;
    int tx = t & 15, ty = t >> 4;
    int i0 = blockIdx.x * 16, j0 = blockIdx.y * 16;
    float acc = 0.f;
    for (int s = 0; s < S_DIM; s++) {
        if (t < 16)      mi[t]      = mask[s * I_DIM + i0 + t];
        else if (t < 32) mj[t - 16] = mask[s * I_DIM + j0 + (t - 16)];
        __syncthreads();
        acc += mi[ty] * mj[tx];
        __syncthreads();
    }
    g_norm[(i0 + ty) * I_DIM + j0 + tx] = acc;
}

// ---------------- mma.sync m16n8k16 fp16 -> f32 ----------------------------
#define MMA_16816(C, A, B)                                                      \
    asm volatile("mma.sync.aligned.m16n8k16.row.col.f32.f16.f16.f32 "           \
                 "{%0,%1,%2,%3}, {%4,%5,%6,%7}, {%8,%9}, {%0,%1,%2,%3};"        \
                 : "+f"(C[0]), "+f"(C[1]), "+f"(C[2]), "+f"(C[3])               \
                 : "r"(A[0]), "r"(A[1]), "r"(A[2]), "r"(A[3]),                  \
                   "r"(B[0]), "r"(B[1]))

// ---------------- K4: GEMM1  G[(i,d),(j,e)] = L * R^T, K = 128 -------------
// CTA tile 128x128, 8 warps (4 x 2), warp tile 32x64. Smem row pad = 8 halfs.
__global__ __launch_bounds__(256, 2) void k_gemm1() {
    __shared__ __half As[128][72];
    __shared__ __half Bs[128][72];
    int tid = threadIdx.x;
    int lane = tid & 31, wid = tid >> 5;
    int wm = wid & 3, wn = wid >> 2;
    int g = lane >> 2, tg = lane & 3;
    int bm = blockIdx.x, bn = blockIdx.y;
    const __half* Ag = g_L + (size_t)bm * 128 * S_DIM;
    const __half* Bg = g_R + (size_t)bn * 128 * S_DIM;

    float c[2][8][4];
#pragma unroll
    for (int a = 0; a < 2; a++)
#pragma unroll
        for (int b = 0; b < 8; b++)
#pragma unroll
            for (int k = 0; k < 4; k++) c[a][b][k] = 0.f;

#pragma unroll
    for (int kc = 0; kc < 128; kc += 64) {
        __syncthreads();
#pragma unroll
        for (int u = 0; u < 4; u++) {
            int h = (tid + u * 256) * 8;
            int r = h >> 6, cc = h & 63;
            *(uint4*)&As[r][cc] = *(const uint4*)(Ag + r * S_DIM + kc + cc);
            *(uint4*)&Bs[r][cc] = *(const uint4*)(Bg + r * S_DIM + kc + cc);
        }
        __syncthreads();
#pragma unroll
        for (int kk = 0; kk < 4; kk++) {
            int k0 = kk * 16 + tg * 2;
            uint32_t a[2][4], b[8][2];
#pragma unroll
            for (int mi = 0; mi < 2; mi++) {
                int r = wm * 32 + mi * 16 + g;
                a[mi][0] = *(const uint32_t*)&As[r][k0];
                a[mi][1] = *(const uint32_t*)&As[r + 8][k0];
                a[mi][2] = *(const uint32_t*)&As[r][k0 + 8];
                a[mi][3] = *(const uint32_t*)&As[r + 8][k0 + 8];
            }
#pragma unroll
            for (int ni = 0; ni < 8; ni++) {
                int r = wn * 64 + ni * 8 + g;
                b[ni][0] = *(const uint32_t*)&Bs[r][k0];
                b[ni][1] = *(const uint32_t*)&Bs[r][k0 + 8];
            }
#pragma unroll
            for (int mi = 0; mi < 2; mi++)
#pragma unroll
                for (int ni = 0; ni < 8; ni++)
                    MMA_16816(c[mi][ni], a[mi], b[ni]);
        }
    }

    // Epilogue: scatter into G[i][j][d][e] as fp16(rn)
#pragma unroll
    for (int mi = 0; mi < 2; mi++) {
#pragma unroll
        for (int ni = 0; ni < 8; ni++) {
            int r0 = bm * 128 + wm * 32 + mi * 16 + g;
            int n0 = bn * 128 + wn * 64 + ni * 8 + tg * 2;
            int j = n0 >> 5, e = n0 & 31;
            {
                int ii = r0 >> 5, d = r0 & 31;
                __half2 h = __floats2half2_rn(c[mi][ni][0], c[mi][ni][1]);
                *(__half2*)&g_G[(((size_t)ii * I_DIM + j) << 10) + (d << 5) + e] = h;
            }
            {
                int r1 = r0 + 8;
                int ii = r1 >> 5, d = r1 & 31;
                __half2 h = __floats2half2_rn(c[mi][ni][2], c[mi][ni][3]);
                *(__half2*)&g_G[(((size_t)ii * I_DIM + j) << 10) + (d << 5) + e] = h;
            }
        }
    }
}

// ---------------- K5: GEMM2  out[(i,j),f] = G2 * Wt^T + bias, /(norm+1e-3) -
// M = 147456, N = 128 (single tile wide), K = 1024 in 16 chunks of 64.
__global__ __launch_bounds__(256, 2) void k_gemm2(const float* __restrict__ obias,
                                                  float* __restrict__ out) {
    __shared__ __half As[128][72];
    __shared__ __half Bs[128][72];
    int tid = threadIdx.x;
    int lane = tid & 31, wid = tid >> 5;
    int wm = wid & 3, wn = wid >> 2;
    int g = lane >> 2, tg = lane & 3;
    int bm = blockIdx.x;
    const __half* Ag = g_G + (size_t)bm * 128 * 1024;

    float c[2][8][4];
#pragma unroll
    for (int a = 0; a < 2; a++)
#pragma unroll
        for (int b = 0; b < 8; b++)
#pragma unroll
            for (int k = 0; k < 4; k++) c[a][b][k] = 0.f;

    for (int kc = 0; kc < 1024; kc += 64) {
        __syncthreads();
#pragma unroll
        for (int u = 0; u < 4; u++) {
            int h = (tid + u * 256) * 8;
            int r = h >> 6, cc = h & 63;
            *(uint4*)&As[r][cc] = *(const uint4*)(Ag + (size_t)r * 1024 + kc + cc);
            *(uint4*)&Bs[r][cc] = *(const uint4*)(g_Wt + (size_t)r * 1024 + kc + cc);
        }
        __syncthreads();
#pragma unroll
        for (int kk = 0; kk < 4; kk++) {
            int k0 = kk * 16 + tg * 2;
            uint32_t a[2][4], b[8][2];
#pragma unroll
            for (int mi = 0; mi < 2; mi++) {
                int r = wm * 32 + mi * 16 + g;
                a[mi][0] = *(const uint32_t*)&As[r][k0];
                a[mi][1] = *(const uint32_t*)&As[r + 8][k0];
                a[mi][2] = *(const uint32_t*)&As[r][k0 + 8];
                a[mi][3] = *(const uint32_t*)&As[r + 8][k0 + 8];
            }
#pragma unroll
            for (int ni = 0; ni < 8; ni++) {
                int r = wn * 64 + ni * 8 + g;
                b[ni][0] = *(const uint32_t*)&Bs[r][k0];
                b[ni][1] = *(const uint32_t*)&Bs[r][k0 + 8];
            }
#pragma unroll
            for (int mi = 0; mi < 2; mi++)
#pragma unroll
                for (int ni = 0; ni < 8; ni++)
                    MMA_16816(c[mi][ni], a[mi], b[ni]);
        }
    }

    // Epilogue: (+bias) / (norm + 0.001)
#pragma unroll
    for (int mi = 0; mi < 2; mi++) {
        int p0 = bm * 128 + wm * 32 + mi * 16 + g;
        float rn0 = 1.f / (g_norm[p0] + 0.001f);
        float rn1 = 1.f / (g_norm[p0 + 8] + 0.001f);
#pragma unroll
        for (int ni = 0; ni < 8; ni++) {
            int f = wn * 64 + ni * 8 + tg * 2;
            float2 bias = *(const float2*)&obias[f];
            float2 o0, o1;
            o0.x = (c[mi][ni][0] + bias.x) * rn0;
            o0.y = (c[mi][ni][1] + bias.y) * rn0;
            o1.x = (c[mi][ni][2] + bias.x) * rn1;
            o1.y = (c[mi][ni][3] + bias.y) * rn1;
            *(float2*)&out[(size_t)p0 * F_DIM + f] = o0;
            *(float2*)&out[(size_t)(p0 + 8) * F_DIM + f] = o1;
        }
    }
}

// ---------------- launch ---------------------------------------------------
extern "C" void kernel_launch(void* const* d_in, const int* in_sizes, int n_in,
                              void* d_out, int out_size) {
    (void)in_sizes; (void)n_in; (void)out_size;
    const float* node = (const float*)d_in[0];   // (128,384,256)
    const float* mask = (const float*)d_in[1];   // (128,384)
    const float* Wp   = (const float*)d_in[2];   // (256,64)
    const float* bp   = (const float*)d_in[3];   // (64,)
    const float* Wo   = (const float*)d_in[4];   // (32,32,128)
    const float* ob   = (const float*)d_in[5];   // (128,)
    float* out = (float*)d_out;                  // (384,384,128)

    k_ln_proj<<<S_DIM * I_DIM, 256>>>(node, mask, Wp, bp);
    k_wt<<<(F_DIM * 1024) / 256, 256>>>(Wo);
    k_norm<<<dim3(I_DIM / 16, I_DIM / 16), 256>>>(mask);
    k_gemm1<<<dim3(MROWS / 128, MROWS / 128), 256>>>();
    k_gemm2<<<(I_DIM * I_DIM) / 128, 256>>>(ob, out);
}